// round 14
// baseline (speedup 1.0000x reference)
#include <cuda_runtime.h>
#include <cuda_bf16.h>
#include <math.h>

// ---------------------------------------------------------------------------
// AdaptiveVoxelization — fused single-kernel, 8 pts/thread voxel role
//   coors[N,3]  : zyx voxel index, -1 if out of range
//   centers[3,R^3], mask[R^3] : adaptive voxel centers (quadratic scaling)
// Output layout (float32 branch): [ coors (N*3) | centers (3*R^3) | mask (R^3) ]
// ---------------------------------------------------------------------------

#define RES   100
#define R3    1000000          // RES^3
#define CEN_QUADS (R3 / 4)     // 250000 threads, 4 k-consecutive cells each

// point_cloud_range
#define PCR_X0 (-50.0f)
#define PCR_Y0 (-50.0f)
#define PCR_Z0 ( -1.0f)
#define PCR_X1 (150.0f)
#define PCR_Y1 ( 50.0f)
#define PCR_Z1 (  3.0f)

// voxel size / grid (grid = round((hi-lo)/vs) in f32 == {2000,1000,20})
#define VSX 0.1f
#define VSY 0.1f
#define VSZ 0.2f
#define GX 2000.0f
#define GY 1000.0f
#define GZ   20.0f

#define SCALING 25.0f
#define TPB 256

// ---------------- shared device helpers ------------------------------------

__device__ __forceinline__ void voxelize_one(float px, float py, float pz,
                                             float& o0, float& o1, float& o2) {
    // bit-exact vs reference: rn subtract, rn divide, floor
    float fx = floorf(__fdiv_rn(__fsub_rn(px, PCR_X0), VSX));
    float fy = floorf(__fdiv_rn(__fsub_rn(py, PCR_Y0), VSY));
    float fz = floorf(__fdiv_rn(__fsub_rn(pz, PCR_Z0), VSZ));
    bool valid = (fx >= 0.0f) && (fx < GX) &&
                 (fy >= 0.0f) && (fy < GY) &&
                 (fz >= 0.0f) && (fz < GZ);
    o0 = valid ? fz : -1.0f;   // zyx order
    o1 = valid ? fy : -1.0f;
    o2 = valid ? fx : -1.0f;
}

__device__ __forceinline__ float lin_val(float start, float delta, int i) {
    // matches jnp.linspace: start + i * delta, no FMA contraction
    return __fadd_rn(start, __fmul_rn((float)i, delta));
}

__device__ __forceinline__ float norm3(float x, float y, float z) {
    float s = __fadd_rn(__fadd_rn(__fmul_rn(x, x), __fmul_rn(y, y)),
                        __fmul_rn(z, z));
    return __fsqrt_rn(s);
}

// ---------------- fused kernel ---------------------------------------------

__global__ void fused_kernel(const float4* __restrict__ pts,
                             float4* __restrict__ coors,     // N*3 floats
                             float*  __restrict__ centers,   // 3*R3 floats
                             float*  __restrict__ mask,      // R3 floats
                             int nocts, int cenBlocks) {
    int b = blockIdx.x;

    if (b < cenBlocks) {
        // ---- centers role: 4 consecutive k-cells per thread ----
        int t = b * TPB + threadIdx.x;
        if (t >= CEN_QUADS) return;

        const float dx = (PCR_X1 - PCR_X0) / 99.0f;
        const float dy = (PCR_Y1 - PCR_Y0) / 99.0f;
        const float dz = (PCR_Z1 - PCR_Z0) / 99.0f;

        int i  = t / 2500;            // t = i*2500 + j*25 + kq
        int r0 = t - i * 2500;
        int j  = r0 / 25;
        int kq = r0 - j * 25;
        int k4 = kq * 4;

        float x = lin_val(PCR_X0, dx, i);
        float y = lin_val(PCR_Y0, dy, j);

        // norm_c from the 8 linspace corners (monotone rounding -> grid max)
        float xe0 = lin_val(PCR_X0, dx, 0),  xe1 = lin_val(PCR_X0, dx, 99);
        float ye0 = lin_val(PCR_Y0, dy, 0),  ye1 = lin_val(PCR_Y0, dy, 99);
        float ze0 = lin_val(PCR_Z0, dz, 0),  ze1 = lin_val(PCR_Z0, dz, 99);
        float nc = 0.0f;
#pragma unroll
        for (int cb = 0; cb < 8; cb++) {
            float cx = (cb & 1) ? xe1 : xe0;
            float cy = (cb & 2) ? ye1 : ye0;
            float cz = (cb & 4) ? ze1 : ze0;
            nc = fmaxf(nc, norm3(cx, cy, cz));
        }
        float nc2 = __fmul_rn(nc, nc);

        float cx[4], cy[4], cz[4], mk[4];
#pragma unroll
        for (int q = 0; q < 4; q++) {
            float z   = lin_val(PCR_Z0, dz, k4 + q);
            float nrm = norm3(x, y, z);
            float sf  = __fdiv_rn(__fmul_rn(nrm, nrm), nc2);
            float fac = __fadd_rn(1.0f, __fmul_rn(sf, SCALING));
            float vx  = __fmul_rn(x, fac);
            float vy  = __fmul_rn(y, fac);
            float vz  = __fmul_rn(z, fac);
            bool m = (vx >= PCR_X0) && (vx <= PCR_X1) &&
                     (vy >= PCR_Y0) && (vy <= PCR_Y1) &&
                     (vz >= PCR_Z0) && (vz <= PCR_Z1);
            cx[q] = vx; cy[q] = vy; cz[q] = vz; mk[q] = m ? 1.0f : 0.0f;
        }

        int idx4 = t;  // float4 index; base offsets R3, 2*R3 are %4==0
        ((float4*)centers)[idx4]              = make_float4(cx[0], cx[1], cx[2], cx[3]);
        ((float4*)(centers + R3))[idx4]       = make_float4(cy[0], cy[1], cy[2], cy[3]);
        ((float4*)(centers + 2 * R3))[idx4]   = make_float4(cz[0], cz[1], cz[2], cz[3]);
        ((float4*)mask)[idx4]                 = make_float4(mk[0], mk[1], mk[2], mk[3]);
        return;
    }

    // ---- voxelize role: 8 points per thread (oct) ----
    int t = (b - cenBlocks) * TPB + threadIdx.x;
    if (t >= nocts) return;

    const float4* p = pts + (size_t)8 * t;
    float4 a[8];
#pragma unroll
    for (int r = 0; r < 8; r++)
        a[r] = __ldcs(p + r);           // streaming load: evict-first

    float c[24];
#pragma unroll
    for (int r = 0; r < 8; r++)
        voxelize_one(a[r].x, a[r].y, a[r].z,
                     c[3 * r + 0], c[3 * r + 1], c[3 * r + 2]);

    float4* q = coors + (size_t)6 * t;
#pragma unroll
    for (int r = 0; r < 6; r++)
        __stcs(q + r, make_float4(c[4 * r + 0], c[4 * r + 1],
                                  c[4 * r + 2], c[4 * r + 3]));  // streaming store
}

// ---------------- scalar tail (N % 8 != 0 only) ----------------------------

__global__ void voxelize_tail_f(const float* __restrict__ pts,
                                float* __restrict__ out, int start, int npts) {
    int i = start + blockIdx.x * blockDim.x + threadIdx.x;
    if (i >= npts) return;
    float o0, o1, o2;
    voxelize_one(pts[4 * i + 0], pts[4 * i + 1], pts[4 * i + 2], o0, o1, o2);
    out[3 * (size_t)i + 0] = o0;
    out[3 * (size_t)i + 1] = o1;
    out[3 * (size_t)i + 2] = o2;
}

// ---------------- int32-only fallback branch -------------------------------

__global__ void voxelize_i4(const float4* __restrict__ pts,
                            int4* __restrict__ out, int nquads) {
    int t = blockIdx.x * blockDim.x + threadIdx.x;
    if (t >= nquads) return;
    int c[12];
#pragma unroll
    for (int r = 0; r < 4; r++) {
        float4 p = pts[4 * t + r];
        float o0, o1, o2;
        voxelize_one(p.x, p.y, p.z, o0, o1, o2);
        c[3 * r + 0] = (int)o0; c[3 * r + 1] = (int)o1; c[3 * r + 2] = (int)o2;
    }
    int4* q = out + (size_t)3 * t;
    q[0] = make_int4(c[0], c[1], c[2],  c[3]);
    q[1] = make_int4(c[4], c[5], c[6],  c[7]);
    q[2] = make_int4(c[8], c[9], c[10], c[11]);
}

__global__ void voxelize_tail_i(const float* __restrict__ pts,
                                int* __restrict__ out, int start, int npts) {
    int i = start + blockIdx.x * blockDim.x + threadIdx.x;
    if (i >= npts) return;
    float o0, o1, o2;
    voxelize_one(pts[4 * i + 0], pts[4 * i + 1], pts[4 * i + 2], o0, o1, o2);
    out[3 * (size_t)i + 0] = (int)o0;
    out[3 * (size_t)i + 1] = (int)o1;
    out[3 * (size_t)i + 2] = (int)o2;
}

// ---------------------------------------------------------------------------

extern "C" void kernel_launch(void* const* d_in, const int* in_sizes, int n_in,
                              void* d_out, int out_size) {
    const float* pts = (const float*)d_in[0];
    const int npts   = in_sizes[0] / 4;      // [N,4]
    const int nocts  = npts / 8;
    const int rem    = npts - nocts * 8;

    const size_t coors_elems = (size_t)npts * 3;

    if ((size_t)out_size >= coors_elems + 4 * (size_t)R3) {
        // float32 concat layout: [coors | centers | mask]
        float* out     = (float*)d_out;
        float* centers = out + coors_elems;
        float* mask    = centers + 3 * (size_t)R3;

        const int cenBlocks = (CEN_QUADS + TPB - 1) / TPB;   // 977
        const int voxBlocks = (nocts + TPB - 1) / TPB;       // 1954 for N=4M
        fused_kernel<<<cenBlocks + voxBlocks, TPB>>>(
            (const float4*)pts, (float4*)out, centers, mask, nocts, cenBlocks);
        if (rem > 0)
            voxelize_tail_f<<<1, 32>>>(pts, out, nocts * 8, npts);
    } else {
        // coors-only int32 layout
        int* out = (int*)d_out;
        const int nquads = npts / 4;
        const int rem4   = npts - nquads * 4;
        if (nquads > 0)
            voxelize_i4<<<(nquads + TPB - 1) / TPB, TPB>>>(
                (const float4*)pts, (int4*)out, nquads);
        if (rem4 > 0)
            voxelize_tail_i<<<1, 32>>>(pts, out, nquads * 4, npts);
    }
}

// round 15
// speedup vs baseline: 1.0849x; 1.0849x over previous
#include <cuda_runtime.h>
#include <cuda_bf16.h>
#include <math.h>

// ---------------------------------------------------------------------------
// AdaptiveVoxelization — fused kernel, persistent grid-stride voxel role
//   coors[N,3]  : zyx voxel index, -1 if out of range
//   centers[3,R^3], mask[R^3] : adaptive voxel centers (quadratic scaling)
// Output layout (float32 branch): [ coors (N*3) | centers (3*R^3) | mask (R^3) ]
// ---------------------------------------------------------------------------

#define RES   100
#define R3    1000000          // RES^3
#define CEN_QUADS (R3 / 4)     // 250000 threads, 4 k-consecutive cells each

// point_cloud_range
#define PCR_X0 (-50.0f)
#define PCR_Y0 (-50.0f)
#define PCR_Z0 ( -1.0f)
#define PCR_X1 (150.0f)
#define PCR_Y1 ( 50.0f)
#define PCR_Z1 (  3.0f)

// voxel size / grid (grid = round((hi-lo)/vs) in f32 == {2000,1000,20})
#define VSX 0.1f
#define VSY 0.1f
#define VSZ 0.2f
#define GX 2000.0f
#define GY 1000.0f
#define GZ   20.0f

#define SCALING 25.0f
#define TPB 256
#define VOX_BLOCKS (148 * 8)   // one full resident wave at regs<=32

// ---------------- shared device helpers ------------------------------------

__device__ __forceinline__ void voxelize_one(float px, float py, float pz,
                                             float& o0, float& o1, float& o2) {
    // bit-exact vs reference: rn subtract, rn divide, floor
    float fx = floorf(__fdiv_rn(__fsub_rn(px, PCR_X0), VSX));
    float fy = floorf(__fdiv_rn(__fsub_rn(py, PCR_Y0), VSY));
    float fz = floorf(__fdiv_rn(__fsub_rn(pz, PCR_Z0), VSZ));
    bool valid = (fx >= 0.0f) && (fx < GX) &&
                 (fy >= 0.0f) && (fy < GY) &&
                 (fz >= 0.0f) && (fz < GZ);
    o0 = valid ? fz : -1.0f;   // zyx order
    o1 = valid ? fy : -1.0f;
    o2 = valid ? fx : -1.0f;
}

__device__ __forceinline__ float lin_val(float start, float delta, int i) {
    // matches jnp.linspace: start + i * delta, no FMA contraction
    return __fadd_rn(start, __fmul_rn((float)i, delta));
}

__device__ __forceinline__ float norm3(float x, float y, float z) {
    float s = __fadd_rn(__fadd_rn(__fmul_rn(x, x), __fmul_rn(y, y)),
                        __fmul_rn(z, z));
    return __fsqrt_rn(s);
}

// ---------------- fused kernel ---------------------------------------------

__global__ void __launch_bounds__(TPB)
fused_kernel(const float4* __restrict__ pts,
             float4* __restrict__ coors,     // N*3 floats
             float*  __restrict__ centers,   // 3*R3 floats
             float*  __restrict__ mask,      // R3 floats
             int nquads, int cenBlocks, int voxBlocks) {
    int b = blockIdx.x;

    if (b < cenBlocks) {
        // ---- centers role: 4 consecutive k-cells per thread ----
        int t = b * TPB + threadIdx.x;
        if (t >= CEN_QUADS) return;

        const float dx = (PCR_X1 - PCR_X0) / 99.0f;
        const float dy = (PCR_Y1 - PCR_Y0) / 99.0f;
        const float dz = (PCR_Z1 - PCR_Z0) / 99.0f;

        int i  = t / 2500;            // t = i*2500 + j*25 + kq
        int r0 = t - i * 2500;
        int j  = r0 / 25;
        int kq = r0 - j * 25;
        int k4 = kq * 4;

        float x = lin_val(PCR_X0, dx, i);
        float y = lin_val(PCR_Y0, dy, j);

        // norm_c from the 8 linspace corners (monotone rounding -> grid max)
        float xe0 = lin_val(PCR_X0, dx, 0),  xe1 = lin_val(PCR_X0, dx, 99);
        float ye0 = lin_val(PCR_Y0, dy, 0),  ye1 = lin_val(PCR_Y0, dy, 99);
        float ze0 = lin_val(PCR_Z0, dz, 0),  ze1 = lin_val(PCR_Z0, dz, 99);
        float nc = 0.0f;
#pragma unroll
        for (int cb = 0; cb < 8; cb++) {
            float cx = (cb & 1) ? xe1 : xe0;
            float cy = (cb & 2) ? ye1 : ye0;
            float cz = (cb & 4) ? ze1 : ze0;
            nc = fmaxf(nc, norm3(cx, cy, cz));
        }
        float nc2 = __fmul_rn(nc, nc);

        float cx[4], cy[4], cz[4], mk[4];
#pragma unroll
        for (int q = 0; q < 4; q++) {
            float z   = lin_val(PCR_Z0, dz, k4 + q);
            float nrm = norm3(x, y, z);
            float sf  = __fdiv_rn(__fmul_rn(nrm, nrm), nc2);
            float fac = __fadd_rn(1.0f, __fmul_rn(sf, SCALING));
            float vx  = __fmul_rn(x, fac);
            float vy  = __fmul_rn(y, fac);
            float vz  = __fmul_rn(z, fac);
            bool m = (vx >= PCR_X0) && (vx <= PCR_X1) &&
                     (vy >= PCR_Y0) && (vy <= PCR_Y1) &&
                     (vz >= PCR_Z0) && (vz <= PCR_Z1);
            cx[q] = vx; cy[q] = vy; cz[q] = vz; mk[q] = m ? 1.0f : 0.0f;
        }

        int idx4 = t;  // float4 index; base offsets R3, 2*R3 are %4==0
        ((float4*)centers)[idx4]              = make_float4(cx[0], cx[1], cx[2], cx[3]);
        ((float4*)(centers + R3))[idx4]       = make_float4(cy[0], cy[1], cy[2], cy[3]);
        ((float4*)(centers + 2 * R3))[idx4]   = make_float4(cz[0], cz[1], cz[2], cz[3]);
        ((float4*)mask)[idx4]                 = make_float4(mk[0], mk[1], mk[2], mk[3]);
        return;
    }

    // ---- voxelize role: persistent grid-stride, 4 points per iteration ----
    int stride = voxBlocks * TPB;
    for (int t = (b - cenBlocks) * TPB + threadIdx.x; t < nquads; t += stride) {
        const float4* p = pts + (size_t)4 * t;
        float4 a0 = p[0], a1 = p[1], a2 = p[2], a3 = p[3];
        float c[12];
        voxelize_one(a0.x, a0.y, a0.z, c[0], c[1],  c[2]);
        voxelize_one(a1.x, a1.y, a1.z, c[3], c[4],  c[5]);
        voxelize_one(a2.x, a2.y, a2.z, c[6], c[7],  c[8]);
        voxelize_one(a3.x, a3.y, a3.z, c[9], c[10], c[11]);
        float4* q = coors + (size_t)3 * t;
        q[0] = make_float4(c[0], c[1], c[2],  c[3]);
        q[1] = make_float4(c[4], c[5], c[6],  c[7]);
        q[2] = make_float4(c[8], c[9], c[10], c[11]);
    }
}

// ---------------- scalar tail (N % 4 != 0 only) ----------------------------

__global__ void voxelize_tail_f(const float* __restrict__ pts,
                                float* __restrict__ out, int start, int npts) {
    int i = start + blockIdx.x * blockDim.x + threadIdx.x;
    if (i >= npts) return;
    float o0, o1, o2;
    voxelize_one(pts[4 * i + 0], pts[4 * i + 1], pts[4 * i + 2], o0, o1, o2);
    out[3 * (size_t)i + 0] = o0;
    out[3 * (size_t)i + 1] = o1;
    out[3 * (size_t)i + 2] = o2;
}

// ---------------- int32-only fallback branch -------------------------------

__global__ void voxelize_i4(const float4* __restrict__ pts,
                            int4* __restrict__ out, int nquads) {
    int t = blockIdx.x * blockDim.x + threadIdx.x;
    if (t >= nquads) return;
    int c[12];
#pragma unroll
    for (int r = 0; r < 4; r++) {
        float4 p = pts[4 * t + r];
        float o0, o1, o2;
        voxelize_one(p.x, p.y, p.z, o0, o1, o2);
        c[3 * r + 0] = (int)o0; c[3 * r + 1] = (int)o1; c[3 * r + 2] = (int)o2;
    }
    int4* q = out + (size_t)3 * t;
    q[0] = make_int4(c[0], c[1], c[2],  c[3]);
    q[1] = make_int4(c[4], c[5], c[6],  c[7]);
    q[2] = make_int4(c[8], c[9], c[10], c[11]);
}

__global__ void voxelize_tail_i(const float* __restrict__ pts,
                                int* __restrict__ out, int start, int npts) {
    int i = start + blockIdx.x * blockDim.x + threadIdx.x;
    if (i >= npts) return;
    float o0, o1, o2;
    voxelize_one(pts[4 * i + 0], pts[4 * i + 1], pts[4 * i + 2], o0, o1, o2);
    out[3 * (size_t)i + 0] = (int)o0;
    out[3 * (size_t)i + 1] = (int)o1;
    out[3 * (size_t)i + 2] = (int)o2;
}

// ---------------------------------------------------------------------------

extern "C" void kernel_launch(void* const* d_in, const int* in_sizes, int n_in,
                              void* d_out, int out_size) {
    const float* pts = (const float*)d_in[0];
    const int npts   = in_sizes[0] / 4;      // [N,4]
    const int nquads = npts / 4;
    const int rem    = npts - nquads * 4;

    const size_t coors_elems = (size_t)npts * 3;

    if ((size_t)out_size >= coors_elems + 4 * (size_t)R3) {
        // float32 concat layout: [coors | centers | mask]
        float* out     = (float*)d_out;
        float* centers = out + coors_elems;
        float* mask    = centers + 3 * (size_t)R3;

        const int cenBlocks = (CEN_QUADS + TPB - 1) / TPB;   // 977
        int voxBlocks = VOX_BLOCKS;                          // 1184 persistent
        int needed = (nquads + TPB - 1) / TPB;
        if (needed < voxBlocks) voxBlocks = needed;          // small-N safety
        fused_kernel<<<cenBlocks + voxBlocks, TPB>>>(
            (const float4*)pts, (float4*)out, centers, mask,
            nquads, cenBlocks, voxBlocks);
        if (rem > 0)
            voxelize_tail_f<<<1, 32>>>(pts, out, nquads * 4, npts);
    } else {
        // coors-only int32 layout
        int* out = (int*)d_out;
        if (nquads > 0)
            voxelize_i4<<<(nquads + TPB - 1) / TPB, TPB>>>(
                (const float4*)pts, (int4*)out, nquads);
        if (rem > 0)
            voxelize_tail_i<<<1, 32>>>(pts, out, nquads * 4, npts);
    }
}

// round 16
// speedup vs baseline: 1.2153x; 1.1202x over previous
#include <cuda_runtime.h>
#include <cuda_bf16.h>
#include <math.h>

// ---------------------------------------------------------------------------
// AdaptiveVoxelization — fused kernel, guarded fast-division voxel role
//   coors[N,3]  : zyx voxel index, -1 if out of range
//   centers[3,R^3], mask[R^3] : adaptive voxel centers (quadratic scaling)
// Output layout (float32 branch): [ coors (N*3) | centers (3*R^3) | mask (R^3) ]
//
// Voxel fast path: q = (p-lo)*rvs (rvs = rn(1/vs)); floor via magic-add.
// Guard: |q_mul - q_div| <= 2.8e-4 for |q|<=2210, so when frac(q) is in
// [1/1024, 1-1/1024] the floors provably agree; otherwise recompute with the
// exact div.rn (P ~ 2e-3 per value) -> output bit-identical to __fdiv_rn path.
// ---------------------------------------------------------------------------

#define RES   100
#define R3    1000000          // RES^3
#define CEN_QUADS (R3 / 4)     // 250000 threads, 4 k-consecutive cells each

// point_cloud_range
#define PCR_X0 (-50.0f)
#define PCR_Y0 (-50.0f)
#define PCR_Z0 ( -1.0f)
#define PCR_X1 (150.0f)
#define PCR_Y1 ( 50.0f)
#define PCR_Z1 (  3.0f)

// voxel size / grid (grid = round((hi-lo)/vs) in f32 == {2000,1000,20})
#define VSX 0.1f
#define VSY 0.1f
#define VSZ 0.2f
#define GX 2000.0f
#define GY 1000.0f
#define GZ   20.0f
// rn(1/0.1f) == 10.0f, rn(1/0.2f) == 5.0f (verified against fp32 rounding)
#define RVSX 10.0f
#define RVSY 10.0f
#define RVSZ  5.0f

#define SCALING 25.0f
#define TPB 256

#define MAGIC   12582912.0f          // 2^23 + 2^22 : integer-grid anchor
#define MARGIN  0.0009765625f        // 1/1024 > 2.8e-4 worst-case |q_mul-q_div|

// ---------------- shared device helpers ------------------------------------

// floor(q) exactly, for |q| < 2^22, via round-down magic add (2 x FADD)
__device__ __forceinline__ float fast_floor(float q) {
    return __fadd_rn(__fadd_rd(q, MAGIC), -MAGIC);
}

// floor((p - lo)/vs) matching floorf(__fdiv_rn(...)) bit-exactly.
__device__ __forceinline__ float vox_coord(float p, float lo, float vs, float rvs) {
    float aa = __fsub_rn(p, lo);
    float qa = __fmul_rn(aa, rvs);
    float fl = fast_floor(qa);
    float fr = __fsub_rn(qa, fl);                       // exact
    if (fr < MARGIN || fr > (1.0f - MARGIN))            // rare (~2e-3)
        fl = floorf(__fdiv_rn(aa, vs));                 // exact reference path
    return fl;
}

__device__ __forceinline__ void voxelize_one(float px, float py, float pz,
                                             float& o0, float& o1, float& o2) {
    float fx = vox_coord(px, PCR_X0, VSX, RVSX);
    float fy = vox_coord(py, PCR_Y0, VSY, RVSY);
    float fz = vox_coord(pz, PCR_Z0, VSZ, RVSZ);
    bool valid = (fx >= 0.0f) && (fx < GX) &&
                 (fy >= 0.0f) && (fy < GY) &&
                 (fz >= 0.0f) && (fz < GZ);
    o0 = valid ? fz : -1.0f;   // zyx order
    o1 = valid ? fy : -1.0f;
    o2 = valid ? fx : -1.0f;
}

__device__ __forceinline__ float lin_val(float start, float delta, int i) {
    // matches jnp.linspace: start + i * delta, no FMA contraction
    return __fadd_rn(start, __fmul_rn((float)i, delta));
}

__device__ __forceinline__ float norm3(float x, float y, float z) {
    float s = __fadd_rn(__fadd_rn(__fmul_rn(x, x), __fmul_rn(y, y)),
                        __fmul_rn(z, z));
    return __fsqrt_rn(s);
}

// ---------------- fused kernel ---------------------------------------------

__global__ void __launch_bounds__(TPB)
fused_kernel(const float4* __restrict__ pts,
             float4* __restrict__ coors,     // N*3 floats
             float*  __restrict__ centers,   // 3*R3 floats
             float*  __restrict__ mask,      // R3 floats
             int nquads, int cenBlocks) {
    int b = blockIdx.x;

    if (b < cenBlocks) {
        // ---- centers role: 4 consecutive k-cells per thread ----
        int t = b * TPB + threadIdx.x;
        if (t >= CEN_QUADS) return;

        const float dx = (PCR_X1 - PCR_X0) / 99.0f;
        const float dy = (PCR_Y1 - PCR_Y0) / 99.0f;
        const float dz = (PCR_Z1 - PCR_Z0) / 99.0f;

        int i  = t / 2500;            // t = i*2500 + j*25 + kq
        int r0 = t - i * 2500;
        int j  = r0 / 25;
        int kq = r0 - j * 25;
        int k4 = kq * 4;

        float x = lin_val(PCR_X0, dx, i);
        float y = lin_val(PCR_Y0, dy, j);

        // norm_c from the 8 linspace corners (monotone rounding -> grid max)
        float xe0 = lin_val(PCR_X0, dx, 0),  xe1 = lin_val(PCR_X0, dx, 99);
        float ye0 = lin_val(PCR_Y0, dy, 0),  ye1 = lin_val(PCR_Y0, dy, 99);
        float ze0 = lin_val(PCR_Z0, dz, 0),  ze1 = lin_val(PCR_Z0, dz, 99);
        float nc = 0.0f;
#pragma unroll
        for (int cb = 0; cb < 8; cb++) {
            float cx = (cb & 1) ? xe1 : xe0;
            float cy = (cb & 2) ? ye1 : ye0;
            float cz = (cb & 4) ? ze1 : ze0;
            nc = fmaxf(nc, norm3(cx, cy, cz));
        }
        float nc2 = __fmul_rn(nc, nc);

        float cx[4], cy[4], cz[4], mk[4];
#pragma unroll
        for (int q = 0; q < 4; q++) {
            float z   = lin_val(PCR_Z0, dz, k4 + q);
            float nrm = norm3(x, y, z);
            float sf  = __fdiv_rn(__fmul_rn(nrm, nrm), nc2);
            float fac = __fadd_rn(1.0f, __fmul_rn(sf, SCALING));
            float vx  = __fmul_rn(x, fac);
            float vy  = __fmul_rn(y, fac);
            float vz  = __fmul_rn(z, fac);
            bool m = (vx >= PCR_X0) && (vx <= PCR_X1) &&
                     (vy >= PCR_Y0) && (vy <= PCR_Y1) &&
                     (vz >= PCR_Z0) && (vz <= PCR_Z1);
            cx[q] = vx; cy[q] = vy; cz[q] = vz; mk[q] = m ? 1.0f : 0.0f;
        }

        int idx4 = t;  // float4 index; base offsets R3, 2*R3 are %4==0
        ((float4*)centers)[idx4]              = make_float4(cx[0], cx[1], cx[2], cx[3]);
        ((float4*)(centers + R3))[idx4]       = make_float4(cy[0], cy[1], cy[2], cy[3]);
        ((float4*)(centers + 2 * R3))[idx4]   = make_float4(cz[0], cz[1], cz[2], cz[3]);
        ((float4*)mask)[idx4]                 = make_float4(mk[0], mk[1], mk[2], mk[3]);
        return;
    }

    // ---- voxelize role: 4 points per thread ----
    int t = (b - cenBlocks) * TPB + threadIdx.x;
    if (t >= nquads) return;
    const float4* p = pts + (size_t)4 * t;
    float4 a0 = p[0], a1 = p[1], a2 = p[2], a3 = p[3];
    float c[12];
    voxelize_one(a0.x, a0.y, a0.z, c[0], c[1],  c[2]);
    voxelize_one(a1.x, a1.y, a1.z, c[3], c[4],  c[5]);
    voxelize_one(a2.x, a2.y, a2.z, c[6], c[7],  c[8]);
    voxelize_one(a3.x, a3.y, a3.z, c[9], c[10], c[11]);
    float4* q = coors + (size_t)3 * t;
    q[0] = make_float4(c[0], c[1], c[2],  c[3]);
    q[1] = make_float4(c[4], c[5], c[6],  c[7]);
    q[2] = make_float4(c[8], c[9], c[10], c[11]);
}

// ---------------- scalar tail (N % 4 != 0 only) ----------------------------

__global__ void voxelize_tail_f(const float* __restrict__ pts,
                                float* __restrict__ out, int start, int npts) {
    int i = start + blockIdx.x * blockDim.x + threadIdx.x;
    if (i >= npts) return;
    float o0, o1, o2;
    voxelize_one(pts[4 * i + 0], pts[4 * i + 1], pts[4 * i + 2], o0, o1, o2);
    out[3 * (size_t)i + 0] = o0;
    out[3 * (size_t)i + 1] = o1;
    out[3 * (size_t)i + 2] = o2;
}

// ---------------- int32-only fallback branch -------------------------------

__global__ void voxelize_i4(const float4* __restrict__ pts,
                            int4* __restrict__ out, int nquads) {
    int t = blockIdx.x * blockDim.x + threadIdx.x;
    if (t >= nquads) return;
    int c[12];
#pragma unroll
    for (int r = 0; r < 4; r++) {
        float4 p = pts[4 * t + r];
        float o0, o1, o2;
        voxelize_one(p.x, p.y, p.z, o0, o1, o2);
        c[3 * r + 0] = (int)o0; c[3 * r + 1] = (int)o1; c[3 * r + 2] = (int)o2;
    }
    int4* q = out + (size_t)3 * t;
    q[0] = make_int4(c[0], c[1], c[2],  c[3]);
    q[1] = make_int4(c[4], c[5], c[6],  c[7]);
    q[2] = make_int4(c[8], c[9], c[10], c[11]);
}

__global__ void voxelize_tail_i(const float* __restrict__ pts,
                                int* __restrict__ out, int start, int npts) {
    int i = start + blockIdx.x * blockDim.x + threadIdx.x;
    if (i >= npts) return;
    float o0, o1, o2;
    voxelize_one(pts[4 * i + 0], pts[4 * i + 1], pts[4 * i + 2], o0, o1, o2);
    out[3 * (size_t)i + 0] = (int)o0;
    out[3 * (size_t)i + 1] = (int)o1;
    out[3 * (size_t)i + 2] = (int)o2;
}

// ---------------------------------------------------------------------------

extern "C" void kernel_launch(void* const* d_in, const int* in_sizes, int n_in,
                              void* d_out, int out_size) {
    const float* pts = (const float*)d_in[0];
    const int npts   = in_sizes[0] / 4;      // [N,4]
    const int nquads = npts / 4;
    const int rem    = npts - nquads * 4;

    const size_t coors_elems = (size_t)npts * 3;

    if ((size_t)out_size >= coors_elems + 4 * (size_t)R3) {
        // float32 concat layout: [coors | centers | mask]
        float* out     = (float*)d_out;
        float* centers = out + coors_elems;
        float* mask    = centers + 3 * (size_t)R3;

        const int cenBlocks = (CEN_QUADS + TPB - 1) / TPB;   // 977
        const int voxBlocks = (nquads + TPB - 1) / TPB;      // 3907 for N=4M
        fused_kernel<<<cenBlocks + voxBlocks, TPB>>>(
            (const float4*)pts, (float4*)out, centers, mask, nquads, cenBlocks);
        if (rem > 0)
            voxelize_tail_f<<<1, 32>>>(pts, out, nquads * 4, npts);
    } else {
        // coors-only int32 layout
        int* out = (int*)d_out;
        if (nquads > 0)
            voxelize_i4<<<(nquads + TPB - 1) / TPB, TPB>>>(
                (const float4*)pts, (int4*)out, nquads);
        if (rem > 0)
            voxelize_tail_i<<<1, 32>>>(pts, out, nquads * 4, npts);
    }
}

// round 17
// speedup vs baseline: 1.2637x; 1.0398x over previous
#include <cuda_runtime.h>
#include <cuda_bf16.h>
#include <math.h>

// ---------------------------------------------------------------------------
// AdaptiveVoxelization — fused kernel, guarded fast division, vox-first order
//   coors[N,3]  : zyx voxel index, -1 if out of range
//   centers[3,R^3], mask[R^3] : adaptive voxel centers (quadratic scaling)
// Output layout (float32 branch): [ coors (N*3) | centers (3*R^3) | mask (R^3) ]
//
// Voxel fast path: q = (p-lo)*rvs (rvs = rn(1/vs)); floor via magic-add.
// Guard: |q_mul - q_div| <= 2.8e-4 for |q|<=2210, so when frac(q) is at least
// 1/1024 away from both 0 and 1 the floors provably agree; otherwise recompute
// with exact div.rn (P ~ 2e-3 per value) -> bit-identical to __fdiv_rn path.
//
// Block order: vox blocks first (long, DRAM-bound), centers blocks last
// (short, compute-bound) so the final partial wave is made of short blocks.
// ---------------------------------------------------------------------------

#define RES   100
#define R3    1000000          // RES^3
#define CEN_QUADS (R3 / 4)     // 250000 threads, 4 k-consecutive cells each

// point_cloud_range
#define PCR_X0 (-50.0f)
#define PCR_Y0 (-50.0f)
#define PCR_Z0 ( -1.0f)
#define PCR_X1 (150.0f)
#define PCR_Y1 ( 50.0f)
#define PCR_Z1 (  3.0f)

// voxel size / grid (grid = round((hi-lo)/vs) in f32 == {2000,1000,20})
#define VSX 0.1f
#define VSY 0.1f
#define VSZ 0.2f
#define GX 2000.0f
#define GY 1000.0f
#define GZ   20.0f
// rn(1/0.1f) == 10.0f, rn(1/0.2f) == 5.0f (verified against fp32 rounding)
#define RVSX 10.0f
#define RVSY 10.0f
#define RVSZ  5.0f

#define SCALING 25.0f
#define TPB 256

#define MAGIC   12582912.0f          // 2^23 + 2^22 : integer-grid anchor
#define MARGIN  0.0009765625f        // 1/1024 > 2.8e-4 worst-case |q_mul-q_div|

// ---------------- shared device helpers ------------------------------------

// floor(q) exactly, for |q| < 2^22, via round-down magic add (2 x FADD)
__device__ __forceinline__ float fast_floor(float q) {
    return __fadd_rn(__fadd_rd(q, MAGIC), -MAGIC);
}

// floor((p - lo)/vs) matching floorf(__fdiv_rn(...)) bit-exactly.
__device__ __forceinline__ float vox_coord(float p, float lo, float vs, float rvs) {
    float aa = __fsub_rn(p, lo);
    float qa = __fmul_rn(aa, rvs);
    float fl = fast_floor(qa);
    float fr = __fsub_rn(qa, fl);                       // exact
    // unsafe iff frac within MARGIN of 0 or 1: single compare via |fr-0.5|
    if (fabsf(__fsub_rn(fr, 0.5f)) > (0.5f - MARGIN))   // rare (~2e-3)
        fl = floorf(__fdiv_rn(aa, vs));                 // exact reference path
    return fl;
}

__device__ __forceinline__ void voxelize_one(float px, float py, float pz,
                                             float& o0, float& o1, float& o2) {
    float fx = vox_coord(px, PCR_X0, VSX, RVSX);
    float fy = vox_coord(py, PCR_Y0, VSY, RVSY);
    float fz = vox_coord(pz, PCR_Z0, VSZ, RVSZ);
    bool valid = (fx >= 0.0f) && (fx < GX) &&
                 (fy >= 0.0f) && (fy < GY) &&
                 (fz >= 0.0f) && (fz < GZ);
    o0 = valid ? fz : -1.0f;   // zyx order
    o1 = valid ? fy : -1.0f;
    o2 = valid ? fx : -1.0f;
}

__device__ __forceinline__ float lin_val(float start, float delta, int i) {
    // matches jnp.linspace: start + i * delta, no FMA contraction
    return __fadd_rn(start, __fmul_rn((float)i, delta));
}

__device__ __forceinline__ float norm3(float x, float y, float z) {
    float s = __fadd_rn(__fadd_rn(__fmul_rn(x, x), __fmul_rn(y, y)),
                        __fmul_rn(z, z));
    return __fsqrt_rn(s);
}

// ---------------- fused kernel ---------------------------------------------

__global__ void __launch_bounds__(TPB)
fused_kernel(const float4* __restrict__ pts,
             float4* __restrict__ coors,     // N*3 floats
             float*  __restrict__ centers,   // 3*R3 floats
             float*  __restrict__ mask,      // R3 floats
             int nquads, int voxBlocks) {
    int b = blockIdx.x;

    if (b >= voxBlocks) {
        // ---- centers role (scheduled LAST): 4 consecutive k-cells/thread ----
        int t = (b - voxBlocks) * TPB + threadIdx.x;
        if (t >= CEN_QUADS) return;

        const float dx = (PCR_X1 - PCR_X0) / 99.0f;
        const float dy = (PCR_Y1 - PCR_Y0) / 99.0f;
        const float dz = (PCR_Z1 - PCR_Z0) / 99.0f;

        int i  = t / 2500;            // t = i*2500 + j*25 + kq
        int r0 = t - i * 2500;
        int j  = r0 / 25;
        int kq = r0 - j * 25;
        int k4 = kq * 4;

        float x = lin_val(PCR_X0, dx, i);
        float y = lin_val(PCR_Y0, dy, j);

        // norm_c from the 8 linspace corners (monotone rounding -> grid max)
        float xe0 = lin_val(PCR_X0, dx, 0),  xe1 = lin_val(PCR_X0, dx, 99);
        float ye0 = lin_val(PCR_Y0, dy, 0),  ye1 = lin_val(PCR_Y0, dy, 99);
        float ze0 = lin_val(PCR_Z0, dz, 0),  ze1 = lin_val(PCR_Z0, dz, 99);
        float nc = 0.0f;
#pragma unroll
        for (int cb = 0; cb < 8; cb++) {
            float cx = (cb & 1) ? xe1 : xe0;
            float cy = (cb & 2) ? ye1 : ye0;
            float cz = (cb & 4) ? ze1 : ze0;
            nc = fmaxf(nc, norm3(cx, cy, cz));
        }
        float nc2 = __fmul_rn(nc, nc);

        float cx[4], cy[4], cz[4], mk[4];
#pragma unroll
        for (int q = 0; q < 4; q++) {
            float z   = lin_val(PCR_Z0, dz, k4 + q);
            float nrm = norm3(x, y, z);
            float sf  = __fdiv_rn(__fmul_rn(nrm, nrm), nc2);
            float fac = __fadd_rn(1.0f, __fmul_rn(sf, SCALING));
            float vx  = __fmul_rn(x, fac);
            float vy  = __fmul_rn(y, fac);
            float vz  = __fmul_rn(z, fac);
            bool m = (vx >= PCR_X0) && (vx <= PCR_X1) &&
                     (vy >= PCR_Y0) && (vy <= PCR_Y1) &&
                     (vz >= PCR_Z0) && (vz <= PCR_Z1);
            cx[q] = vx; cy[q] = vy; cz[q] = vz; mk[q] = m ? 1.0f : 0.0f;
        }

        int idx4 = t;  // float4 index; base offsets R3, 2*R3 are %4==0
        ((float4*)centers)[idx4]              = make_float4(cx[0], cx[1], cx[2], cx[3]);
        ((float4*)(centers + R3))[idx4]       = make_float4(cy[0], cy[1], cy[2], cy[3]);
        ((float4*)(centers + 2 * R3))[idx4]   = make_float4(cz[0], cz[1], cz[2], cz[3]);
        ((float4*)mask)[idx4]                 = make_float4(mk[0], mk[1], mk[2], mk[3]);
        return;
    }

    // ---- voxelize role (scheduled FIRST): 4 points per thread ----
    int t = b * TPB + threadIdx.x;
    if (t >= nquads) return;
    const float4* p = pts + (size_t)4 * t;
    float4 a0 = p[0], a1 = p[1], a2 = p[2], a3 = p[3];
    float c[12];
    voxelize_one(a0.x, a0.y, a0.z, c[0], c[1],  c[2]);
    voxelize_one(a1.x, a1.y, a1.z, c[3], c[4],  c[5]);
    voxelize_one(a2.x, a2.y, a2.z, c[6], c[7],  c[8]);
    voxelize_one(a3.x, a3.y, a3.z, c[9], c[10], c[11]);
    float4* q = coors + (size_t)3 * t;
    q[0] = make_float4(c[0], c[1], c[2],  c[3]);
    q[1] = make_float4(c[4], c[5], c[6],  c[7]);
    q[2] = make_float4(c[8], c[9], c[10], c[11]);
}

// ---------------- scalar tail (N % 4 != 0 only) ----------------------------

__global__ void voxelize_tail_f(const float* __restrict__ pts,
                                float* __restrict__ out, int start, int npts) {
    int i = start + blockIdx.x * blockDim.x + threadIdx.x;
    if (i >= npts) return;
    float o0, o1, o2;
    voxelize_one(pts[4 * i + 0], pts[4 * i + 1], pts[4 * i + 2], o0, o1, o2);
    out[3 * (size_t)i + 0] = o0;
    out[3 * (size_t)i + 1] = o1;
    out[3 * (size_t)i + 2] = o2;
}

// ---------------- int32-only fallback branch -------------------------------

__global__ void voxelize_i4(const float4* __restrict__ pts,
                            int4* __restrict__ out, int nquads) {
    int t = blockIdx.x * blockDim.x + threadIdx.x;
    if (t >= nquads) return;
    int c[12];
#pragma unroll
    for (int r = 0; r < 4; r++) {
        float4 p = pts[4 * t + r];
        float o0, o1, o2;
        voxelize_one(p.x, p.y, p.z, o0, o1, o2);
        c[3 * r + 0] = (int)o0; c[3 * r + 1] = (int)o1; c[3 * r + 2] = (int)o2;
    }
    int4* q = out + (size_t)3 * t;
    q[0] = make_int4(c[0], c[1], c[2],  c[3]);
    q[1] = make_int4(c[4], c[5], c[6],  c[7]);
    q[2] = make_int4(c[8], c[9], c[10], c[11]);
}

__global__ void voxelize_tail_i(const float* __restrict__ pts,
                                int* __restrict__ out, int start, int npts) {
    int i = start + blockIdx.x * blockDim.x + threadIdx.x;
    if (i >= npts) return;
    float o0, o1, o2;
    voxelize_one(pts[4 * i + 0], pts[4 * i + 1], pts[4 * i + 2], o0, o1, o2);
    out[3 * (size_t)i + 0] = (int)o0;
    out[3 * (size_t)i + 1] = (int)o1;
    out[3 * (size_t)i + 2] = (int)o2;
}

// ---------------------------------------------------------------------------

extern "C" void kernel_launch(void* const* d_in, const int* in_sizes, int n_in,
                              void* d_out, int out_size) {
    const float* pts = (const float*)d_in[0];
    const int npts   = in_sizes[0] / 4;      // [N,4]
    const int nquads = npts / 4;
    const int rem    = npts - nquads * 4;

    const size_t coors_elems = (size_t)npts * 3;

    if ((size_t)out_size >= coors_elems + 4 * (size_t)R3) {
        // float32 concat layout: [coors | centers | mask]
        float* out     = (float*)d_out;
        float* centers = out + coors_elems;
        float* mask    = centers + 3 * (size_t)R3;

        const int voxBlocks = (nquads + TPB - 1) / TPB;      // 3907 for N=4M
        const int cenBlocks = (CEN_QUADS + TPB - 1) / TPB;   // 977
        fused_kernel<<<voxBlocks + cenBlocks, TPB>>>(
            (const float4*)pts, (float4*)out, centers, mask, nquads, voxBlocks);
        if (rem > 0)
            voxelize_tail_f<<<1, 32>>>(pts, out, nquads * 4, npts);
    } else {
        // coors-only int32 layout
        int* out = (int*)d_out;
        if (nquads > 0)
            voxelize_i4<<<(nquads + TPB - 1) / TPB, TPB>>>(
                (const float4*)pts, (int4*)out, nquads);
        if (rem > 0)
            voxelize_tail_i<<<1, 32>>>(pts, out, nquads * 4, npts);
    }
}